// round 2
// baseline (speedup 1.0000x reference)
#include <cuda_runtime.h>
#include <cuda_bf16.h>

// values[m] = sum_n exp(-0.5 * sum_d (p[m,d]-pos[n,d])^2 * inv_var[n,d]) * I[n]
//
// Per gaussian n, precompute (log2 domain, -0.5*log2e folded in):
//   civ_d = -0.5*log2(e) / (exp(ls_d)^2 + eps)
//   a_d = civ_d,  b_d = -2*civ_d*s_d,  c = sum_d civ_d*s_d^2
//   arg = sum_d (a_d*p_d^2 + b_d*p_d) + c + log2(I)   ; value = exp2(arg)
// The half-constant cc = 0.5*(c + log2 I) is stored in BOTH lanes of a pair so
// a 3-deep fma.rn.f32x2 chain on ((a_d,b_d),(p_d^2,p_d)) pairs followed by
// lo+hi yields arg, and the accumulate is a plain FADD (no intensity load).
//
// smem layout per gaussian (8 floats): ax,bx, ay,by, az,bz, cc,cc

#define MAX_N 4096
__device__ float g_params[8 * MAX_N];

__global__ void prep_kernel(const float* __restrict__ positions,
                            const float* __restrict__ log_scales,
                            const float* __restrict__ intensities,
                            int N) {
    int n = blockIdx.x * blockDim.x + threadIdx.x;
    if (n >= N) return;
    const float LOG2E = 1.4426950408889634f;
    float o[8];
    float c = 0.0f;
#pragma unroll
    for (int d = 0; d < 3; d++) {
        float s = __expf(log_scales[3 * n + d]);
        float civ = -0.5f * LOG2E / (s * s + 1e-6f);
        float p = positions[3 * n + d];
        o[2 * d]     = civ;
        o[2 * d + 1] = -2.0f * civ * p;
        c = fmaf(civ, p * p, c);
    }
    float I = intensities[n];
    float cc = 0.5f * (c + __log2f(I));   // I in [0,0.5): log2(0) = -inf -> exp2 -> 0, still correct
    o[6] = cc;
    o[7] = cc;
#pragma unroll
    for (int i = 0; i < 8; i++) g_params[8 * n + i] = o[i];
}

__device__ __forceinline__ unsigned long long ffma2(unsigned long long a,
                                                    unsigned long long b,
                                                    unsigned long long c) {
    unsigned long long d;
    asm("fma.rn.f32x2 %0, %1, %2, %3;" : "=l"(d) : "l"(a), "l"(b), "l"(c));
    return d;
}

__device__ __forceinline__ unsigned long long pack2(float lo, float hi) {
    unsigned long long d;
    asm("mov.b64 %0, {%1, %2};" : "=l"(d) : "f"(lo), "f"(hi));
    return d;
}

__device__ __forceinline__ float pair_hsum(unsigned long long v) {
    float lo, hi;
    asm("mov.b64 {%0, %1}, %2;" : "=f"(lo), "=f"(hi) : "l"(v));
    return lo + hi;
}

__device__ __forceinline__ float ex2(float x) {
    float r;
    asm("ex2.approx.f32 %0, %1;" : "=f"(r) : "f"(x));
    return r;
}

// block = 128 threads, 2 points per thread -> 256 points/block, grid = 196
__global__ void __launch_bounds__(128)
eval_kernel(const float* __restrict__ points,
            float* __restrict__ out,
            int M, int N) {
    extern __shared__ float sp[];  // 8*N floats = 32KB @ N=1024
    {
        const float4* gp4 = (const float4*)g_params;
        float4* sp4 = (float4*)sp;
        for (int i = threadIdx.x; i < 2 * N; i += blockDim.x) sp4[i] = gp4[i];
    }
    __syncthreads();

    int base = blockIdx.x * 256 + threadIdx.x;
    int m0 = base;
    int m1 = base + 128;

    float px0 = 0.f, py0 = 0.f, pz0 = 0.f;
    float px1 = 0.f, py1 = 0.f, pz1 = 0.f;
    if (m0 < M) { px0 = points[3*m0]; py0 = points[3*m0+1]; pz0 = points[3*m0+2]; }
    if (m1 < M) { px1 = points[3*m1]; py1 = points[3*m1+1]; pz1 = points[3*m1+2]; }

    unsigned long long vx0 = pack2(px0 * px0, px0);
    unsigned long long vy0 = pack2(py0 * py0, py0);
    unsigned long long vz0 = pack2(pz0 * pz0, pz0);
    unsigned long long vx1 = pack2(px1 * px1, px1);
    unsigned long long vy1 = pack2(py1 * py1, py1);
    unsigned long long vz1 = pack2(pz1 * pz1, pz1);

    float acc0 = 0.0f, acc1 = 0.0f;
    const ulonglong2* g = (const ulonglong2*)sp;

#pragma unroll 4
    for (int n = 0; n < N; n++) {
        ulonglong2 u0 = g[2 * n];      // (ax,bx) , (ay,by)
        ulonglong2 u1 = g[2 * n + 1];  // (az,bz) , (cc,cc)

        unsigned long long r0 = ffma2(u0.x, vx0, u1.y);
        unsigned long long r1 = ffma2(u0.x, vx1, u1.y);
        r0 = ffma2(u0.y, vy0, r0);
        r1 = ffma2(u0.y, vy1, r1);
        r0 = ffma2(u1.x, vz0, r0);
        r1 = ffma2(u1.x, vz1, r1);

        float arg0 = pair_hsum(r0);
        float arg1 = pair_hsum(r1);
        acc0 += ex2(arg0);
        acc1 += ex2(arg1);
    }

    if (m0 < M) out[m0] = acc0;
    if (m1 < M) out[m1] = acc1;
}

extern "C" void kernel_launch(void* const* d_in, const int* in_sizes, int n_in,
                              void* d_out, int out_size) {
    const float* points      = (const float*)d_in[0];  // [M,3]
    const float* positions   = (const float*)d_in[1];  // [N,3]
    const float* log_scales  = (const float*)d_in[2];  // [N,3]
    const float* intensities = (const float*)d_in[3];  // [N]
    float* out = (float*)d_out;

    int M = in_sizes[0] / 3;
    int N = in_sizes[3];

    prep_kernel<<<(N + 255) / 256, 256>>>(positions, log_scales, intensities, N);

    int ptsPerBlock = 256;
    int grid = (M + ptsPerBlock - 1) / ptsPerBlock;
    size_t smem = (size_t)8 * N * sizeof(float);
    eval_kernel<<<grid, 128, smem>>>(points, out, M, N);
}

// round 3
// speedup vs baseline: 1.8551x; 1.8551x over previous
#include <cuda_runtime.h>
#include <cuda_bf16.h>

// values[m] = sum_n exp(-0.5 * sum_d (p[m,d]-pos[n,d])^2 * inv_var[n,d]) * I[n]
//
// Per gaussian n, precompute (log2 domain, -0.5*log2e folded in):
//   civ_d = -0.5*log2(e) / (exp(ls_d)^2 + eps)
//   a_d = civ_d,  b_d = -2*civ_d*s_d
//   cc  = 0.5*(sum_d civ_d*s_d^2 + log2 I)   (stored in both lanes)
//   arg = sum_d (a_d*p_d^2 + b_d*p_d) + 2*cc ; value = exp2(arg)
// 3-deep fma.rn.f32x2 chain on ((a_d,b_d),(p_d^2,p_d)) pairs, lo+hi, ex2, add.
//
// smem per gaussian (8 floats): ax,bx, ay,by, az,bz, cc,cc
//
// eval: block = 512 threads = 128 points x 4 gaussian-segments.
// Each segment processes N/4 gaussians; partials combined via smem reduction.
// grid = ceil(M/128) = 391 -> ~48 warps/SM resident (latency fully hidden).

#define MAX_N 4096
__device__ float g_params[8 * MAX_N];

__global__ void prep_kernel(const float* __restrict__ positions,
                            const float* __restrict__ log_scales,
                            const float* __restrict__ intensities,
                            int N) {
    int n = blockIdx.x * blockDim.x + threadIdx.x;
    if (n >= N) return;
    const float LOG2E = 1.4426950408889634f;
    float o[8];
    float c = 0.0f;
#pragma unroll
    for (int d = 0; d < 3; d++) {
        float s = __expf(log_scales[3 * n + d]);
        float civ = -0.5f * LOG2E / (s * s + 1e-6f);
        float p = positions[3 * n + d];
        o[2 * d]     = civ;
        o[2 * d + 1] = -2.0f * civ * p;
        c = fmaf(civ, p * p, c);
    }
    float I = intensities[n];
    float cc = 0.5f * (c + __log2f(I));  // I in [0,0.5): log2(0)=-inf -> exp2 -> 0, correct
    o[6] = cc;
    o[7] = cc;
#pragma unroll
    for (int i = 0; i < 8; i++) g_params[8 * n + i] = o[i];
}

__device__ __forceinline__ unsigned long long ffma2(unsigned long long a,
                                                    unsigned long long b,
                                                    unsigned long long c) {
    unsigned long long d;
    asm("fma.rn.f32x2 %0, %1, %2, %3;" : "=l"(d) : "l"(a), "l"(b), "l"(c));
    return d;
}

__device__ __forceinline__ unsigned long long pack2(float lo, float hi) {
    unsigned long long d;
    asm("mov.b64 %0, {%1, %2};" : "=l"(d) : "f"(lo), "f"(hi));
    return d;
}

__device__ __forceinline__ float pair_hsum(unsigned long long v) {
    float lo, hi;
    asm("mov.b64 {%0, %1}, %2;" : "=f"(lo), "=f"(hi) : "l"(v));
    return lo + hi;
}

__device__ __forceinline__ float ex2(float x) {
    float r;
    asm("ex2.approx.f32 %0, %1;" : "=f"(r) : "f"(x));
    return r;
}

#define PTS_PER_BLOCK 128
#define SEGS 4
#define BLOCK_THREADS (PTS_PER_BLOCK * SEGS)

__global__ void __launch_bounds__(BLOCK_THREADS)
eval_kernel(const float* __restrict__ points,
            float* __restrict__ out,
            int M, int N) {
    extern __shared__ float sp[];  // 8*N params floats + BLOCK_THREADS reduction floats
    {
        const float4* gp4 = (const float4*)g_params;
        float4* sp4 = (float4*)sp;
        for (int i = threadIdx.x; i < 2 * N; i += BLOCK_THREADS) sp4[i] = gp4[i];
    }
    __syncthreads();

    int pt  = threadIdx.x & (PTS_PER_BLOCK - 1);
    int seg = threadIdx.x >> 7;  // log2(PTS_PER_BLOCK)
    int m = blockIdx.x * PTS_PER_BLOCK + pt;

    float px = 0.f, py = 0.f, pz = 0.f;
    if (m < M) {
        px = points[3 * m + 0];
        py = points[3 * m + 1];
        pz = points[3 * m + 2];
    }
    unsigned long long vx = pack2(px * px, px);
    unsigned long long vy = pack2(py * py, py);
    unsigned long long vz = pack2(pz * pz, pz);

    int chunk = N / SEGS;
    const ulonglong2* g = (const ulonglong2*)sp + (size_t)seg * chunk * 2;

    float acc = 0.0f;
#pragma unroll 8
    for (int n = 0; n < chunk; n++) {
        ulonglong2 u0 = g[2 * n];      // (ax,bx) , (ay,by)
        ulonglong2 u1 = g[2 * n + 1];  // (az,bz) , (cc,cc)
        unsigned long long r = ffma2(u0.x, vx, u1.y);
        r = ffma2(u0.y, vy, r);
        r = ffma2(u1.x, vz, r);
        acc += ex2(pair_hsum(r));
    }

    // combine the 4 segment partials
    float* red = sp + 8 * N;
    red[threadIdx.x] = acc;
    __syncthreads();
    if (threadIdx.x < PTS_PER_BLOCK && m < M) {
        float s = red[threadIdx.x]
                + red[threadIdx.x + PTS_PER_BLOCK]
                + red[threadIdx.x + 2 * PTS_PER_BLOCK]
                + red[threadIdx.x + 3 * PTS_PER_BLOCK];
        out[m] = s;
    }
}

extern "C" void kernel_launch(void* const* d_in, const int* in_sizes, int n_in,
                              void* d_out, int out_size) {
    const float* points      = (const float*)d_in[0];  // [M,3]
    const float* positions   = (const float*)d_in[1];  // [N,3]
    const float* log_scales  = (const float*)d_in[2];  // [N,3]
    const float* intensities = (const float*)d_in[3];  // [N]
    float* out = (float*)d_out;

    int M = in_sizes[0] / 3;
    int N = in_sizes[3];

    prep_kernel<<<(N + 255) / 256, 256>>>(positions, log_scales, intensities, N);

    int grid = (M + PTS_PER_BLOCK - 1) / PTS_PER_BLOCK;
    size_t smem = (size_t)8 * N * sizeof(float) + BLOCK_THREADS * sizeof(float);
    eval_kernel<<<grid, BLOCK_THREADS, smem>>>(points, out, M, N);
}